// round 14
// baseline (speedup 1.0000x reference)
#include <cuda_runtime.h>
#include <cuda_fp16.h>
#include <math.h>
#include <stdint.h>

#define N_PTS 8192
#define HDIM  512
#define NM1   8191
#define DEPTHM1 5

// ---------------- scratch (device globals; no allocations allowed) ----------
__device__ __align__(16) __half g_A0[N_PTS * HDIM];
__device__ __align__(16) __half g_A1[N_PTS * HDIM];
__device__ __align__(16) __half g_Wh[DEPTHM1 * HDIM * HDIM];  // [l][k][n] fp16
__device__ float  g_y[N_PTS * 5];
__device__ float  g_ws[NM1];
__device__ float  g_conv[NM1 * 5];
__device__ float  g_par[6];
__device__ double g_acc;
__device__ unsigned int g_done;   // zero-init; self-resetting each replay

// fp16x2 HW tanh: 1 MUFU op per TWO elements (input already fp16-quantized,
// so the approx error sits below the existing activation storage noise)
__device__ __forceinline__ uint32_t tanh2(float x0, float x1) {
    __half2 h = __floats2half2_rn(x0, x1);
    uint32_t r = *(uint32_t*)&h;
    asm("tanh.approx.f16x2 %0, %0;" : "+r"(r));
    return r;
}

// ---------------- prep: params + ws + conv zero + wsplit + layer0 (fused) ----
__global__ void prep_kernel(const float* __restrict__ t, const float* __restrict__ W_in,
                            const float* __restrict__ b_in, const float* __restrict__ Wh,
                            const float* __restrict__ rb, const float* __restrict__ rs,
                            const float* __restrict__ rg, const float* __restrict__ rm,
                            const float* __restrict__ za_p) {
    const int idx  = blockIdx.x * blockDim.x + threadIdx.x;
    const int nthr = gridDim.x * blockDim.x;

    if (idx == 0) {
        float alpha = 0.6f + 0.4f * (1.0f / (1.0f + expf(-za_p[0])));
        g_par[0] = alpha;
        g_par[1] = log1pf(expf(rb[0]));
        g_par[2] = log1pf(expf(rs[0]));
        g_par[3] = log1pf(expf(rg[0]));
        g_par[4] = log1pf(expf(rm[0]));
        g_par[5] = powf(0.1f, -alpha) / expf(lgammaf(2.0f - alpha));
        g_acc    = 0.0;
        g_done   = 0u;
    }

    // Caputo L1 weights (double precision to avoid cancellation)
    if (idx < NM1) {
        float alpha = 0.6f + 0.4f * (1.0f / (1.0f + expf(-za_p[0])));
        double ex = 1.0 - (double)alpha;
        double w = pow((double)(idx + 1), ex);
        if (idx > 0) w -= pow((double)idx, ex);
        g_ws[idx] = (float)w;
    }

    for (int i = idx; i < NM1 * 5; i += nthr) g_conv[i] = 0.0f;

    // weights -> fp16 (8 elems per step)
    for (int v = idx; v < (DEPTHM1 * HDIM * HDIM) / 8; v += nthr) {
        int i = v * 8;
        float4 w0 = *(const float4*)(Wh + i);
        float4 w1 = *(const float4*)(Wh + i + 4);
        __half2 h0 = __floats2half2_rn(w0.x, w0.y);
        __half2 h1 = __floats2half2_rn(w0.z, w0.w);
        __half2 h2 = __floats2half2_rn(w1.x, w1.y);
        __half2 h3 = __floats2half2_rn(w1.z, w1.w);
        *(uint4*)(g_Wh + i) = make_uint4(*(uint32_t*)&h0, *(uint32_t*)&h1,
                                         *(uint32_t*)&h2, *(uint32_t*)&h3);
    }

    // layer 0: h = tanh(t*W_in + b_in) -> fp16 (4 elems per step, f16x2 tanh)
    for (int v = idx; v < (N_PTS * HDIM) / 4; v += nthr) {
        int i   = v * 4;
        int row = i >> 9;
        int j   = i & 511;
        float tv = __ldg(t + row);
        float4 w = *(const float4*)(W_in + j);
        float4 b = *(const float4*)(b_in + j);
        uint32_t r01 = tanh2(fmaf(tv, w.x, b.x), fmaf(tv, w.y, b.y));
        uint32_t r23 = tanh2(fmaf(tv, w.z, b.z), fmaf(tv, w.w, b.w));
        *(uint2*)(g_A0 + i) = make_uint2(r01, r23);
    }
}

// ---------------- tensor-core GEMM (fp16 single-pass) + bias + tanh ----------
// CTA 128m x 128n, BK=16, 8 warps (4m x 2n), warp 32m x 64n, 2 CTAs/SM.
// 8-stage cp.async ring, 8KB/stage (A 4K | B 4K), ONE barrier per iteration.
#define STAGE_BYTES 8192
#define NSTAGE 8
#define GEMM_SMEM (NSTAGE * STAGE_BYTES)

#define LDSM4(r, addr) asm volatile( \
    "ldmatrix.sync.aligned.m8n8.x4.shared.b16 {%0,%1,%2,%3}, [%4];" \
    : "=r"(r[0]), "=r"(r[1]), "=r"(r[2]), "=r"(r[3]) : "r"(addr))

#define LDSM4T(r, addr) asm volatile( \
    "ldmatrix.sync.aligned.m8n8.x4.trans.shared.b16 {%0,%1,%2,%3}, [%4];" \
    : "=r"(r[0]), "=r"(r[1]), "=r"(r[2]), "=r"(r[3]) : "r"(addr))

#define MMAH(d, a, b0, b1) asm volatile( \
    "mma.sync.aligned.m16n8k16.row.col.f32.f16.f16.f32 " \
    "{%0,%1,%2,%3},{%4,%5,%6,%7},{%8,%9},{%0,%1,%2,%3};" \
    : "+f"(d[0]), "+f"(d[1]), "+f"(d[2]), "+f"(d[3]) \
    : "r"(a[0]), "r"(a[1]), "r"(a[2]), "r"(a[3]), "r"(b0), "r"(b1))

__device__ __forceinline__ void cp16(uint32_t dst, const void* src) {
    asm volatile("cp.async.cg.shared.global [%0], [%1], 16;" :: "r"(dst), "l"(src));
}

__global__ __launch_bounds__(256, 2)
void gemm_fp16_kernel(const __half* __restrict__ A,
                      const __half* __restrict__ B,
                      const float* __restrict__ bias,
                      __half* __restrict__ C) {
    extern __shared__ __align__(128) unsigned char smem[];
    const int tid  = threadIdx.x;
    const int lane = tid & 31;
    const int wid  = tid >> 5;
    const int wm   = wid & 3;
    const int wn   = wid >> 2;
    const int rowBase = blockIdx.y * 128;
    const int colBase = blockIdx.x * 128;
    const uint32_t smemBase = (uint32_t)__cvta_generic_to_shared(smem);

    const int arow = tid >> 1;
    const int akq  = (tid & 1) * 8;
    const __half* aSrc = A + (size_t)(rowBase + arow) * HDIM + akq;
    const uint32_t aDst = (uint32_t)(arow * 32) +
                          ((((uint32_t)(akq >> 3)) ^ ((arow >> 2) & 1)) << 4);
    const int bk  = tid >> 4;
    const int bnq = (tid & 15) * 8;
    const __half* bSrc = B + (size_t)bk * HDIM + colBase + bnq;
    const uint32_t bDst = 4096u + bk * 256 + ((((uint32_t)(bnq >> 3)) ^ (bk & 7)) << 4);

    float acc[2][8][4];
#pragma unroll
    for (int i = 0; i < 2; i++)
#pragma unroll
        for (int j = 0; j < 8; j++)
#pragma unroll
            for (int r = 0; r < 4; r++) acc[i][j][r] = 0.0f;

#pragma unroll
    for (int s = 0; s < NSTAGE - 1; s++) {
        uint32_t st = smemBase + s * STAGE_BYTES;
        cp16(st + aDst, aSrc + (s << 4));
        cp16(st + bDst, bSrc + ((size_t)s << 13));
        asm volatile("cp.async.commit_group;");
    }

    int bufC = 0;
    int bufP = NSTAGE - 1;
    for (int s = 0; s < 32; s++) {
        asm volatile("cp.async.wait_group 6;");
        __syncthreads();

        {
            int k0 = ((s + NSTAGE - 1) & 31) << 4;
            uint32_t st = smemBase + bufP * STAGE_BYTES;
            cp16(st + aDst, aSrc + k0);
            cp16(st + bDst, bSrc + ((size_t)k0 << 9));
            asm volatile("cp.async.commit_group;");
            if (++bufP == NSTAGE) bufP = 0;
        }

        const uint32_t st = smemBase + bufC * STAGE_BYTES;
        if (++bufC == NSTAGE) bufC = 0;

        uint32_t a[2][4];
#pragma unroll
        for (int i = 0; i < 2; i++) {
            int r = wm * 32 + i * 16 + (lane & 15);
            uint32_t c = ((uint32_t)(lane >> 4)) ^ ((r >> 2) & 1);
            LDSM4(a[i], st + r * 32 + (c << 4));
        }
        uint32_t b[4][4];
#pragma unroll
        for (int j = 0; j < 4; j++) {
            int kr = lane & 15;
            uint32_t c = ((uint32_t)(wn * 8 + j * 2 + (lane >> 4))) ^ (kr & 7);
            LDSM4T(b[j], st + 4096u + kr * 256 + (c << 4));
        }
#pragma unroll
        for (int i = 0; i < 2; i++) {
#pragma unroll
            for (int j = 0; j < 4; j++) {
                MMAH(acc[i][2 * j],     a[i], b[j][0], b[j][1]);
                MMAH(acc[i][2 * j + 1], a[i], b[j][2], b[j][3]);
            }
        }
    }

    // ---- epilogue: bias + f16x2 HW tanh -> fp16 ----
#pragma unroll
    for (int i = 0; i < 2; i++) {
        int r0 = rowBase + wm * 32 + i * 16 + (lane >> 2);
#pragma unroll
        for (int jn = 0; jn < 8; jn++) {
            int c0 = colBase + wn * 64 + jn * 8 + (lane & 3) * 2;
            float bv0 = __ldg(bias + c0), bv1 = __ldg(bias + c0 + 1);
#pragma unroll
            for (int half = 0; half < 2; half++) {
                int r = r0 + half * 8;
                uint32_t hv = tanh2(acc[i][jn][2 * half + 0] + bv0,
                                    acc[i][jn][2 * half + 1] + bv1);
                *(uint32_t*)(C + (size_t)r * HDIM + c0) = hv;
            }
        }
    }
}

// ---------------- head + softmax (4 halves/iter) ------------------------------
__global__ void head_kernel(const __half* __restrict__ h,
                            const float* __restrict__ W_out, const float* __restrict__ b_out) {
    int gw = (blockIdx.x * blockDim.x + threadIdx.x) >> 5;
    int lane = threadIdx.x & 31;
    if (gw >= N_PTS) return;
    const __half* hr = h + (size_t)gw * HDIM;
    float a0 = 0, a1 = 0, a2 = 0, a3 = 0, a4 = 0;
#pragma unroll
    for (int k = lane * 4; k < HDIM; k += 128) {
        uint2 raw = *(const uint2*)(hr + k);
        __half2 p01 = *(__half2*)&raw.x;
        __half2 p23 = *(__half2*)&raw.y;
        float h0 = __low2float(p01), h1 = __high2float(p01);
        float h2 = __low2float(p23), h3 = __high2float(p23);
        const float* w = W_out + k * 5;
        a0 += h0 * w[0] + h1 * w[5] + h2 * w[10] + h3 * w[15];
        a1 += h0 * w[1] + h1 * w[6] + h2 * w[11] + h3 * w[16];
        a2 += h0 * w[2] + h1 * w[7] + h2 * w[12] + h3 * w[17];
        a3 += h0 * w[3] + h1 * w[8] + h2 * w[13] + h3 * w[18];
        a4 += h0 * w[4] + h1 * w[9] + h2 * w[14] + h3 * w[19];
    }
#pragma unroll
    for (int off = 16; off; off >>= 1) {
        a0 += __shfl_down_sync(~0u, a0, off); a1 += __shfl_down_sync(~0u, a1, off);
        a2 += __shfl_down_sync(~0u, a2, off); a3 += __shfl_down_sync(~0u, a3, off);
        a4 += __shfl_down_sync(~0u, a4, off);
    }
    if (lane == 0) {
        a0 += b_out[0]; a1 += b_out[1]; a2 += b_out[2]; a3 += b_out[3]; a4 += b_out[4];
        float mx = fmaxf(fmaxf(fmaxf(a0, a1), fmaxf(a2, a3)), a4);
        float e0 = expf(a0 - mx), e1 = expf(a1 - mx), e2 = expf(a2 - mx);
        float e3 = expf(a3 - mx), e4 = expf(a4 - mx);
        float inv = 1.0f / (e0 + e1 + e2 + e3 + e4);
        g_y[gw * 5 + 0] = e0 * inv; g_y[gw * 5 + 1] = e1 * inv; g_y[gw * 5 + 2] = e2 * inv;
        g_y[gw * 5 + 3] = e3 * inv; g_y[gw * 5 + 4] = e4 * inv;
    }
}

// ---------------- causal Toeplitz conv (dpsi computed inline from y) ---------
__global__ void conv_kernel() {
    int rx = blockIdx.x, jy = blockIdx.y;
    int M0 = rx * 512, j0 = jy * 256;
    if (j0 > M0 + 511) return;
    __shared__ float sws[768];
    __shared__ float sd[256][8];
    int tid = threadIdx.x;
    int wbase = M0 - j0 - 255;
    for (int k = tid; k < 768; k += 256) {
        int wi = wbase + k;
        sws[k] = (wi >= 0 && wi < NM1) ? g_ws[wi] : 0.0f;
    }
    {
        int j = j0 + tid;
        float d0 = 0, d1 = 0, d2 = 0, d3 = 0, d4 = 0;
        if (j < NM1) {
            const float* yp = &g_y[j * 5];
            d0 = yp[5] - yp[0]; d1 = yp[6] - yp[1]; d2 = yp[7] - yp[2];
            d3 = yp[8] - yp[3]; d4 = yp[9] - yp[4];
        }
        *(float4*)&sd[tid][0] = make_float4(d0, d1, d2, d3);
        sd[tid][4] = d4;
    }
    __syncthreads();

    float p0 = 0, p1 = 0, p2 = 0, p3 = 0, p4 = 0;
    float q0 = 0, q1 = 0, q2 = 0, q3 = 0, q4 = 0;
#pragma unroll 4
    for (int jj = 0; jj < 256; jj++) {
        float4 d = *(float4*)&sd[jj][0];
        float d4 = sd[jj][4];
        float w0 = sws[tid + 255 - jj];
        float w1 = sws[tid + 511 - jj];
        p0 += w0 * d.x; p1 += w0 * d.y; p2 += w0 * d.z; p3 += w0 * d.w; p4 += w0 * d4;
        q0 += w1 * d.x; q1 += w1 * d.y; q2 += w1 * d.z; q3 += w1 * d.w; q4 += w1 * d4;
    }
    int m0 = M0 + tid, m1 = M0 + 256 + tid;
    if (m0 < NM1) {
        atomicAdd(&g_conv[m0 * 5 + 0], p0); atomicAdd(&g_conv[m0 * 5 + 1], p1);
        atomicAdd(&g_conv[m0 * 5 + 2], p2); atomicAdd(&g_conv[m0 * 5 + 3], p3);
        atomicAdd(&g_conv[m0 * 5 + 4], p4);
    }
    if (m1 < NM1) {
        atomicAdd(&g_conv[m1 * 5 + 0], q0); atomicAdd(&g_conv[m1 * 5 + 1], q1);
        atomicAdd(&g_conv[m1 * 5 + 2], q2); atomicAdd(&g_conv[m1 * 5 + 3], q3);
        atomicAdd(&g_conv[m1 * 5 + 4], q4);
    }
}

// ---------------- residual + loss + fused finalize ---------------------------
__global__ void resid_kernel(float* __restrict__ out) {
    __shared__ double sm[256];
    int tid = threadIdx.x, row = blockIdx.x * 256 + tid;
    double local = 0.0;
    if (row < N_PTS) {
        float beta = g_par[1], sg = g_par[2], gm = g_par[3], mu = g_par[4], Cc = g_par[5];
        float ys = g_y[row * 5 + 0], ye = g_y[row * 5 + 1], yi = g_y[row * 5 + 2], yd = g_y[row * 5 + 4];
        float inf = beta * ys * yi / (1.0f - yd);
        float f0 = -inf, f1 = inf - sg * ye, f2 = sg * ye - (gm + mu) * yi, f3 = gm * yi, f4 = mu * yi;
        float d0 = 0, d1 = 0, d2 = 0, d3 = 0, d4 = 0;
        if (row > 0) {
            const float* cv = &g_conv[(row - 1) * 5];
            d0 = Cc * cv[0]; d1 = Cc * cv[1]; d2 = Cc * cv[2]; d3 = Cc * cv[3]; d4 = Cc * cv[4];
        }
        float r0 = d0 - f0, r1 = d1 - f1, r2 = d2 - f2, r3 = d3 - f3, r4 = d4 - f4;
        local = (double)r0 * r0 + (double)r1 * r1 + (double)r2 * r2 + (double)r3 * r3 + (double)r4 * r4;
    }
    sm[tid] = local;
    __syncthreads();
    for (int s2 = 128; s2; s2 >>= 1) {
        if (tid < s2) sm[tid] += sm[tid + s2];
        __syncthreads();
    }
    if (tid == 0) {
        atomicAdd(&g_acc, sm[0]);
        __threadfence();
        unsigned int ticket = atomicAdd(&g_done, 1u);
        if (ticket == gridDim.x - 1) {
            out[0] = (float)(g_acc / (double)(N_PTS * 5));
            g_done = 0u;
        }
    }
}

// ---------------- launch -----------------------------------------------------
extern "C" void kernel_launch(void* const* d_in, const int* in_sizes, int n_in,
                              void* d_out, int out_size) {
    const float* t      = (const float*)d_in[0];
    const float* W_in   = (const float*)d_in[1];
    const float* b_in   = (const float*)d_in[2];
    const float* Wh     = (const float*)d_in[3];
    const float* bh     = (const float*)d_in[4];
    const float* W_out  = (const float*)d_in[5];
    const float* b_out  = (const float*)d_in[6];
    const float* rbeta  = (const float*)d_in[7];
    const float* rsigma = (const float*)d_in[8];
    const float* rgamma = (const float*)d_in[9];
    const float* rmu    = (const float*)d_in[10];
    const float* zalpha = (const float*)d_in[11];
    float* out = (float*)d_out;

    static bool inited = false;
    static __half *a0, *a1, *wh;
    if (!inited) {
        cudaGetSymbolAddress((void**)&a0, g_A0);
        cudaGetSymbolAddress((void**)&a1, g_A1);
        cudaGetSymbolAddress((void**)&wh, g_Wh);
        cudaFuncSetAttribute(gemm_fp16_kernel,
                             cudaFuncAttributeMaxDynamicSharedMemorySize, GEMM_SMEM);
        inited = true;
    }

    prep_kernel<<<1024, 256>>>(t, W_in, b_in, Wh, rbeta, rsigma, rgamma, rmu, zalpha);

    dim3 gg(4, 64);   // (512/128, 8192/128)
    const int WW = HDIM * HDIM;
    gemm_fp16_kernel<<<gg, 256, GEMM_SMEM>>>(a0, wh + 0 * WW, bh + 0 * HDIM, a1);
    gemm_fp16_kernel<<<gg, 256, GEMM_SMEM>>>(a1, wh + 1 * WW, bh + 1 * HDIM, a0);
    gemm_fp16_kernel<<<gg, 256, GEMM_SMEM>>>(a0, wh + 2 * WW, bh + 2 * HDIM, a1);
    gemm_fp16_kernel<<<gg, 256, GEMM_SMEM>>>(a1, wh + 3 * WW, bh + 3 * HDIM, a0);
    gemm_fp16_kernel<<<gg, 256, GEMM_SMEM>>>(a0, wh + 4 * WW, bh + 4 * HDIM, a1);

    head_kernel<<<N_PTS / 8, 256>>>(a1, W_out, b_out);
    conv_kernel<<<dim3(16, 32), 256>>>();
    resid_kernel<<<N_PTS / 256, 256>>>(out);
}

// round 15
// speedup vs baseline: 1.0942x; 1.0942x over previous
#include <cuda_runtime.h>
#include <cuda_fp16.h>
#include <math.h>
#include <stdint.h>

#define N_PTS 8192
#define HDIM  512
#define NM1   8191
#define DEPTHM1 5

// ---------------- scratch (device globals; no allocations allowed) ----------
__device__ __align__(16) __half g_A0[N_PTS * HDIM];
__device__ __align__(16) __half g_A1[N_PTS * HDIM];
__device__ __align__(16) __half g_Wh[DEPTHM1 * HDIM * HDIM];  // [l][k][n] fp16
__device__ float  g_y[N_PTS * 5];
__device__ float  g_ws[NM1];
__device__ float  g_conv[NM1 * 5];
__device__ float  g_par[6];
__device__ double g_acc;
__device__ unsigned int g_done;   // zero-init; self-resetting each replay

// HW tanh (MUFU.TANH f32): 1 MUFU op, rel err ~2^-11 (best measured config)
__device__ __forceinline__ float tanh_fast(float x) {
    float y;
    asm("tanh.approx.f32 %0, %1;" : "=f"(y) : "f"(x));
    return y;
}

// ---------------- prep: params + ws + conv zero + wsplit + layer0 (fused) ----
__global__ void prep_kernel(const float* __restrict__ t, const float* __restrict__ W_in,
                            const float* __restrict__ b_in, const float* __restrict__ Wh,
                            const float* __restrict__ rb, const float* __restrict__ rs,
                            const float* __restrict__ rg, const float* __restrict__ rm,
                            const float* __restrict__ za_p) {
    const int idx  = blockIdx.x * blockDim.x + threadIdx.x;
    const int nthr = gridDim.x * blockDim.x;

    if (idx == 0) {
        float alpha = 0.6f + 0.4f * (1.0f / (1.0f + expf(-za_p[0])));
        g_par[0] = alpha;
        g_par[1] = log1pf(expf(rb[0]));
        g_par[2] = log1pf(expf(rs[0]));
        g_par[3] = log1pf(expf(rg[0]));
        g_par[4] = log1pf(expf(rm[0]));
        g_par[5] = powf(0.1f, -alpha) / expf(lgammaf(2.0f - alpha));
        g_acc    = 0.0;
        g_done   = 0u;
    }

    // Caputo L1 weights (double precision to avoid cancellation)
    if (idx < NM1) {
        float alpha = 0.6f + 0.4f * (1.0f / (1.0f + expf(-za_p[0])));
        double ex = 1.0 - (double)alpha;
        double w = pow((double)(idx + 1), ex);
        if (idx > 0) w -= pow((double)idx, ex);
        g_ws[idx] = (float)w;
    }

    for (int i = idx; i < NM1 * 5; i += nthr) g_conv[i] = 0.0f;

    // weights -> fp16 (8 elems per step)
    for (int v = idx; v < (DEPTHM1 * HDIM * HDIM) / 8; v += nthr) {
        int i = v * 8;
        float4 w0 = *(const float4*)(Wh + i);
        float4 w1 = *(const float4*)(Wh + i + 4);
        __half2 h0 = __floats2half2_rn(w0.x, w0.y);
        __half2 h1 = __floats2half2_rn(w0.z, w0.w);
        __half2 h2 = __floats2half2_rn(w1.x, w1.y);
        __half2 h3 = __floats2half2_rn(w1.z, w1.w);
        *(uint4*)(g_Wh + i) = make_uint4(*(uint32_t*)&h0, *(uint32_t*)&h1,
                                         *(uint32_t*)&h2, *(uint32_t*)&h3);
    }

    // layer 0: h = tanh(t*W_in + b_in) -> fp16 (4 elems per step, f32 tanh)
    for (int v = idx; v < (N_PTS * HDIM) / 4; v += nthr) {
        int i   = v * 4;
        int row = i >> 9;
        int j   = i & 511;
        float tv = __ldg(t + row);
        float4 w = *(const float4*)(W_in + j);
        float4 b = *(const float4*)(b_in + j);
        __half2 h01 = __floats2half2_rn(tanh_fast(fmaf(tv, w.x, b.x)),
                                        tanh_fast(fmaf(tv, w.y, b.y)));
        __half2 h23 = __floats2half2_rn(tanh_fast(fmaf(tv, w.z, b.z)),
                                        tanh_fast(fmaf(tv, w.w, b.w)));
        *(uint2*)(g_A0 + i) = make_uint2(*(uint32_t*)&h01, *(uint32_t*)&h23);
    }
}

// ---------------- tensor-core GEMM (fp16 single-pass) + bias + tanh ----------
// CTA 128m x 128n, BK=16, 8 warps (4m x 2n), warp 32m x 64n, 2 CTAs/SM.
// 8-stage cp.async ring, 8KB/stage (A 4K | B 4K), ONE barrier per iteration.
#define STAGE_BYTES 8192
#define NSTAGE 8
#define GEMM_SMEM (NSTAGE * STAGE_BYTES)

#define LDSM4(r, addr) asm volatile( \
    "ldmatrix.sync.aligned.m8n8.x4.shared.b16 {%0,%1,%2,%3}, [%4];" \
    : "=r"(r[0]), "=r"(r[1]), "=r"(r[2]), "=r"(r[3]) : "r"(addr))

#define LDSM4T(r, addr) asm volatile( \
    "ldmatrix.sync.aligned.m8n8.x4.trans.shared.b16 {%0,%1,%2,%3}, [%4];" \
    : "=r"(r[0]), "=r"(r[1]), "=r"(r[2]), "=r"(r[3]) : "r"(addr))

#define MMAH(d, a, b0, b1) asm volatile( \
    "mma.sync.aligned.m16n8k16.row.col.f32.f16.f16.f32 " \
    "{%0,%1,%2,%3},{%4,%5,%6,%7},{%8,%9},{%0,%1,%2,%3};" \
    : "+f"(d[0]), "+f"(d[1]), "+f"(d[2]), "+f"(d[3]) \
    : "r"(a[0]), "r"(a[1]), "r"(a[2]), "r"(a[3]), "r"(b0), "r"(b1))

__device__ __forceinline__ void cp16(uint32_t dst, const void* src) {
    asm volatile("cp.async.cg.shared.global [%0], [%1], 16;" :: "r"(dst), "l"(src));
}

__global__ __launch_bounds__(256, 2)
void gemm_fp16_kernel(const __half* __restrict__ A,
                      const __half* __restrict__ B,
                      const float* __restrict__ bias,
                      __half* __restrict__ C) {
    extern __shared__ __align__(128) unsigned char smem[];
    const int tid  = threadIdx.x;
    const int lane = tid & 31;
    const int wid  = tid >> 5;
    const int wm   = wid & 3;
    const int wn   = wid >> 2;
    const int rowBase = blockIdx.y * 128;
    const int colBase = blockIdx.x * 128;
    const uint32_t smemBase = (uint32_t)__cvta_generic_to_shared(smem);

    const int arow = tid >> 1;
    const int akq  = (tid & 1) * 8;
    const __half* aSrc = A + (size_t)(rowBase + arow) * HDIM + akq;
    const uint32_t aDst = (uint32_t)(arow * 32) +
                          ((((uint32_t)(akq >> 3)) ^ ((arow >> 2) & 1)) << 4);
    const int bk  = tid >> 4;
    const int bnq = (tid & 15) * 8;
    const __half* bSrc = B + (size_t)bk * HDIM + colBase + bnq;
    const uint32_t bDst = 4096u + bk * 256 + ((((uint32_t)(bnq >> 3)) ^ (bk & 7)) << 4);

    float acc[2][8][4];
#pragma unroll
    for (int i = 0; i < 2; i++)
#pragma unroll
        for (int j = 0; j < 8; j++)
#pragma unroll
            for (int r = 0; r < 4; r++) acc[i][j][r] = 0.0f;

#pragma unroll
    for (int s = 0; s < NSTAGE - 1; s++) {
        uint32_t st = smemBase + s * STAGE_BYTES;
        cp16(st + aDst, aSrc + (s << 4));
        cp16(st + bDst, bSrc + ((size_t)s << 13));
        asm volatile("cp.async.commit_group;");
    }

    int bufC = 0;
    int bufP = NSTAGE - 1;
    for (int s = 0; s < 32; s++) {
        asm volatile("cp.async.wait_group 6;");
        __syncthreads();

        {
            int k0 = ((s + NSTAGE - 1) & 31) << 4;
            uint32_t st = smemBase + bufP * STAGE_BYTES;
            cp16(st + aDst, aSrc + k0);
            cp16(st + bDst, bSrc + ((size_t)k0 << 9));
            asm volatile("cp.async.commit_group;");
            if (++bufP == NSTAGE) bufP = 0;
        }

        const uint32_t st = smemBase + bufC * STAGE_BYTES;
        if (++bufC == NSTAGE) bufC = 0;

        uint32_t a[2][4];
#pragma unroll
        for (int i = 0; i < 2; i++) {
            int r = wm * 32 + i * 16 + (lane & 15);
            uint32_t c = ((uint32_t)(lane >> 4)) ^ ((r >> 2) & 1);
            LDSM4(a[i], st + r * 32 + (c << 4));
        }
        uint32_t b[4][4];
#pragma unroll
        for (int j = 0; j < 4; j++) {
            int kr = lane & 15;
            uint32_t c = ((uint32_t)(wn * 8 + j * 2 + (lane >> 4))) ^ (kr & 7);
            LDSM4T(b[j], st + 4096u + kr * 256 + (c << 4));
        }
#pragma unroll
        for (int i = 0; i < 2; i++) {
#pragma unroll
            for (int j = 0; j < 4; j++) {
                MMAH(acc[i][2 * j],     a[i], b[j][0], b[j][1]);
                MMAH(acc[i][2 * j + 1], a[i], b[j][2], b[j][3]);
            }
        }
    }

    // ---- epilogue: bias + f32 HW tanh -> fp16 ----
#pragma unroll
    for (int i = 0; i < 2; i++) {
        int r0 = rowBase + wm * 32 + i * 16 + (lane >> 2);
#pragma unroll
        for (int jn = 0; jn < 8; jn++) {
            int c0 = colBase + wn * 64 + jn * 8 + (lane & 3) * 2;
            float bv0 = __ldg(bias + c0), bv1 = __ldg(bias + c0 + 1);
#pragma unroll
            for (int half = 0; half < 2; half++) {
                int r = r0 + half * 8;
                float t0 = tanh_fast(acc[i][jn][2 * half + 0] + bv0);
                float t1 = tanh_fast(acc[i][jn][2 * half + 1] + bv1);
                __half2 hv = __floats2half2_rn(t0, t1);
                *(uint32_t*)(C + (size_t)r * HDIM + c0) = *(uint32_t*)&hv;
            }
        }
    }
}

// ---------------- head v2: smem-transposed W_out, 4 rows/warp ----------------
__global__ void head_kernel(const __half* __restrict__ h,
                            const float* __restrict__ W_out, const float* __restrict__ b_out) {
    __shared__ float wT[5][512];
    int tid = threadIdx.x;
    for (int e = tid; e < HDIM * 5; e += 256)
        wT[e % 5][e / 5] = W_out[e];
    __syncthreads();

    int wid = tid >> 5, lane = tid & 31;
    int row0 = (blockIdx.x * 8 + wid) * 4;

    float acc[4][5];
#pragma unroll
    for (int r = 0; r < 4; r++)
#pragma unroll
        for (int c = 0; c < 5; c++) acc[r][c] = 0.0f;

#pragma unroll
    for (int it = 0; it < 4; it++) {
        int k = it * 128 + lane * 4;
        float4 w0 = *(const float4*)&wT[0][k];
        float4 w1 = *(const float4*)&wT[1][k];
        float4 w2 = *(const float4*)&wT[2][k];
        float4 w3 = *(const float4*)&wT[3][k];
        float4 w4 = *(const float4*)&wT[4][k];
#pragma unroll
        for (int r = 0; r < 4; r++) {
            uint2 raw = *(const uint2*)(h + (size_t)(row0 + r) * HDIM + k);
            __half2 p01 = *(__half2*)&raw.x;
            __half2 p23 = *(__half2*)&raw.y;
            float h0 = __low2float(p01), h1 = __high2float(p01);
            float h2 = __low2float(p23), h3 = __high2float(p23);
            acc[r][0] += h0 * w0.x + h1 * w0.y + h2 * w0.z + h3 * w0.w;
            acc[r][1] += h0 * w1.x + h1 * w1.y + h2 * w1.z + h3 * w1.w;
            acc[r][2] += h0 * w2.x + h1 * w2.y + h2 * w2.z + h3 * w2.w;
            acc[r][3] += h0 * w3.x + h1 * w3.y + h2 * w3.z + h3 * w3.w;
            acc[r][4] += h0 * w4.x + h1 * w4.y + h2 * w4.z + h3 * w4.w;
        }
    }

#pragma unroll
    for (int off = 16; off; off >>= 1)
#pragma unroll
        for (int r = 0; r < 4; r++)
#pragma unroll
            for (int c = 0; c < 5; c++)
                acc[r][c] += __shfl_down_sync(~0u, acc[r][c], off);

    if (lane == 0) {
        float b0 = b_out[0], b1 = b_out[1], b2 = b_out[2], b3 = b_out[3], b4 = b_out[4];
#pragma unroll
        for (int r = 0; r < 4; r++) {
            float a0 = acc[r][0] + b0, a1 = acc[r][1] + b1, a2 = acc[r][2] + b2;
            float a3 = acc[r][3] + b3, a4 = acc[r][4] + b4;
            float mx = fmaxf(fmaxf(fmaxf(a0, a1), fmaxf(a2, a3)), a4);
            float e0 = expf(a0 - mx), e1 = expf(a1 - mx), e2 = expf(a2 - mx);
            float e3 = expf(a3 - mx), e4 = expf(a4 - mx);
            float inv = 1.0f / (e0 + e1 + e2 + e3 + e4);
            float* yp = &g_y[(size_t)(row0 + r) * 5];
            yp[0] = e0 * inv; yp[1] = e1 * inv; yp[2] = e2 * inv;
            yp[3] = e3 * inv; yp[4] = e4 * inv;
        }
    }
}

// ---------------- causal Toeplitz conv (dpsi computed inline from y) ---------
__global__ void conv_kernel() {
    int rx = blockIdx.x, jy = blockIdx.y;
    int M0 = rx * 512, j0 = jy * 256;
    if (j0 > M0 + 511) return;
    __shared__ float sws[768];
    __shared__ float sd[256][8];
    int tid = threadIdx.x;
    int wbase = M0 - j0 - 255;
    for (int k = tid; k < 768; k += 256) {
        int wi = wbase + k;
        sws[k] = (wi >= 0 && wi < NM1) ? g_ws[wi] : 0.0f;
    }
    {
        int j = j0 + tid;
        float d0 = 0, d1 = 0, d2 = 0, d3 = 0, d4 = 0;
        if (j < NM1) {
            const float* yp = &g_y[j * 5];
            d0 = yp[5] - yp[0]; d1 = yp[6] - yp[1]; d2 = yp[7] - yp[2];
            d3 = yp[8] - yp[3]; d4 = yp[9] - yp[4];
        }
        *(float4*)&sd[tid][0] = make_float4(d0, d1, d2, d3);
        sd[tid][4] = d4;
    }
    __syncthreads();

    float p0 = 0, p1 = 0, p2 = 0, p3 = 0, p4 = 0;
    float q0 = 0, q1 = 0, q2 = 0, q3 = 0, q4 = 0;
#pragma unroll 4
    for (int jj = 0; jj < 256; jj++) {
        float4 d = *(float4*)&sd[jj][0];
        float d4 = sd[jj][4];
        float w0 = sws[tid + 255 - jj];
        float w1 = sws[tid + 511 - jj];
        p0 += w0 * d.x; p1 += w0 * d.y; p2 += w0 * d.z; p3 += w0 * d.w; p4 += w0 * d4;
        q0 += w1 * d.x; q1 += w1 * d.y; q2 += w1 * d.z; q3 += w1 * d.w; q4 += w1 * d4;
    }
    int m0 = M0 + tid, m1 = M0 + 256 + tid;
    if (m0 < NM1) {
        atomicAdd(&g_conv[m0 * 5 + 0], p0); atomicAdd(&g_conv[m0 * 5 + 1], p1);
        atomicAdd(&g_conv[m0 * 5 + 2], p2); atomicAdd(&g_conv[m0 * 5 + 3], p3);
        atomicAdd(&g_conv[m0 * 5 + 4], p4);
    }
    if (m1 < NM1) {
        atomicAdd(&g_conv[m1 * 5 + 0], q0); atomicAdd(&g_conv[m1 * 5 + 1], q1);
        atomicAdd(&g_conv[m1 * 5 + 2], q2); atomicAdd(&g_conv[m1 * 5 + 3], q3);
        atomicAdd(&g_conv[m1 * 5 + 4], q4);
    }
}

// ---------------- residual + loss + fused finalize ---------------------------
__global__ void resid_kernel(float* __restrict__ out) {
    __shared__ double sm[256];
    int tid = threadIdx.x, row = blockIdx.x * 256 + tid;
    double local = 0.0;
    if (row < N_PTS) {
        float beta = g_par[1], sg = g_par[2], gm = g_par[3], mu = g_par[4], Cc = g_par[5];
        float ys = g_y[row * 5 + 0], ye = g_y[row * 5 + 1], yi = g_y[row * 5 + 2], yd = g_y[row * 5 + 4];
        float inf = beta * ys * yi / (1.0f - yd);
        float f0 = -inf, f1 = inf - sg * ye, f2 = sg * ye - (gm + mu) * yi, f3 = gm * yi, f4 = mu * yi;
        float d0 = 0, d1 = 0, d2 = 0, d3 = 0, d4 = 0;
        if (row > 0) {
            const float* cv = &g_conv[(row - 1) * 5];
            d0 = Cc * cv[0]; d1 = Cc * cv[1]; d2 = Cc * cv[2]; d3 = Cc * cv[3]; d4 = Cc * cv[4];
        }
        float r0 = d0 - f0, r1 = d1 - f1, r2 = d2 - f2, r3 = d3 - f3, r4 = d4 - f4;
        local = (double)r0 * r0 + (double)r1 * r1 + (double)r2 * r2 + (double)r3 * r3 + (double)r4 * r4;
    }
    sm[tid] = local;
    __syncthreads();
    for (int s2 = 128; s2; s2 >>= 1) {
        if (tid < s2) sm[tid] += sm[tid + s2];
        __syncthreads();
    }
    if (tid == 0) {
        atomicAdd(&g_acc, sm[0]);
        __threadfence();
        unsigned int ticket = atomicAdd(&g_done, 1u);
        if (ticket == gridDim.x - 1) {
            out[0] = (float)(g_acc / (double)(N_PTS * 5));
            g_done = 0u;
        }
    }
}

// ---------------- launch -----------------------------------------------------
extern "C" void kernel_launch(void* const* d_in, const int* in_sizes, int n_in,
                              void* d_out, int out_size) {
    const float* t      = (const float*)d_in[0];
    const float* W_in   = (const float*)d_in[1];
    const float* b_in   = (const float*)d_in[2];
    const float* Wh     = (const float*)d_in[3];
    const float* bh     = (const float*)d_in[4];
    const float* W_out  = (const float*)d_in[5];
    const float* b_out  = (const float*)d_in[6];
    const float* rbeta  = (const float*)d_in[7];
    const float* rsigma = (const float*)d_in[8];
    const float* rgamma = (const float*)d_in[9];
    const float* rmu    = (const float*)d_in[10];
    const float* zalpha = (const float*)d_in[11];
    float* out = (float*)d_out;

    static bool inited = false;
    static __half *a0, *a1, *wh;
    if (!inited) {
        cudaGetSymbolAddress((void**)&a0, g_A0);
        cudaGetSymbolAddress((void**)&a1, g_A1);
        cudaGetSymbolAddress((void**)&wh, g_Wh);
        cudaFuncSetAttribute(gemm_fp16_kernel,
                             cudaFuncAttributeMaxDynamicSharedMemorySize, GEMM_SMEM);
        inited = true;
    }

    prep_kernel<<<1024, 256>>>(t, W_in, b_in, Wh, rbeta, rsigma, rgamma, rmu, zalpha);

    dim3 gg(4, 64);   // (512/128, 8192/128)
    const int WW = HDIM * HDIM;
    gemm_fp16_kernel<<<gg, 256, GEMM_SMEM>>>(a0, wh + 0 * WW, bh + 0 * HDIM, a1);
    gemm_fp16_kernel<<<gg, 256, GEMM_SMEM>>>(a1, wh + 1 * WW, bh + 1 * HDIM, a0);
    gemm_fp16_kernel<<<gg, 256, GEMM_SMEM>>>(a0, wh + 2 * WW, bh + 2 * HDIM, a1);
    gemm_fp16_kernel<<<gg, 256, GEMM_SMEM>>>(a1, wh + 3 * WW, bh + 3 * HDIM, a0);
    gemm_fp16_kernel<<<gg, 256, GEMM_SMEM>>>(a0, wh + 4 * WW, bh + 4 * HDIM, a1);

    head_kernel<<<N_PTS / 32, 256>>>(a1, W_out, b_out);
    conv_kernel<<<dim3(16, 32), 256>>>();
    resid_kernel<<<N_PTS / 256, 256>>>(out);
}